// round 9
// baseline (speedup 1.0000x reference)
#include <cuda_runtime.h>
#include <cstdint>

#define B_    64
#define S_    512
#define DIN   512
#define NCAP  32
#define DCAP  64
#define EPSQ  1e-7f

// ---------------- scratch (device globals; no allocations) ----------------
__device__ uint32_t g_Utf[B_ * S_ * DIN];      // tf32 bits of U (converted once)
__device__ float g_Wt[NCAP * DCAP * DIN];      // W transposed: [n][d][i]
__device__ float g_tp[4 * B_ * DIN];           // partial column sums of U
__device__ float g_w[B_ * DIN * NCAP];         // w[b][i][n]
__device__ float g_l[2 * B_ * S_ * NCAP];      // raw logit partials [ihalf][b][s][n]
__device__ float g_vp[2 * B_ * NCAP * DIN];    // v partials [shalf][b][n][i]

// ---------------- tf32 helpers ----------------
__device__ __forceinline__ uint32_t tf32r(float x) {
    uint32_t r;
    asm("cvt.rna.tf32.f32 %0, %1;" : "=r"(r) : "f"(x));
    return r;
}
__device__ __forceinline__ void mma_tf32(float& c0, float& c1, float& c2, float& c3,
                                         uint32_t a0, uint32_t a1, uint32_t a2, uint32_t a3,
                                         uint32_t b0, uint32_t b1) {
    asm("mma.sync.aligned.m16n8k8.row.col.f32.tf32.tf32.f32 "
        "{%0,%1,%2,%3}, {%4,%5,%6,%7}, {%8,%9}, {%0,%1,%2,%3};"
        : "+f"(c0), "+f"(c1), "+f"(c2), "+f"(c3)
        : "r"(a0), "r"(a1), "r"(a2), "r"(a3), "r"(b0), "r"(b1));
}

// ---------------- prep: blocks 0..255 transpose W; 256..511 colsum U + convert tf32 ----
__global__ __launch_bounds__(256) void prep_k(const float* __restrict__ U,
                                              const float* __restrict__ W) {
    int t = threadIdx.x;
    if (blockIdx.x < 256) {
        int n  = blockIdx.x >> 3;
        int i0 = (blockIdx.x & 7) * 64;
        __shared__ float sm[64 * 65];
        #pragma unroll
        for (int r = 0; r < 16; ++r) {
            int idx = r * 256 + t;
            int d = idx & 63, ii = idx >> 6;
            sm[d * 65 + ii] = W[(size_t)(i0 + ii) * 2048 + n * 64 + d];
        }
        __syncthreads();
        #pragma unroll
        for (int r = 0; r < 16; ++r) {
            int idx = r * 256 + t;
            int ii = idx & 63, d = idx >> 6;
            g_Wt[((size_t)n * 64 + d) * 512 + i0 + ii] = sm[d * 65 + ii];
        }
    } else {
        int idx = blockIdx.x - 256;
        int b = idx & 63, sc = idx >> 6;
        size_t base = ((size_t)b * S_ + sc * 128) * DIN;
        const float2* p = (const float2*)(U + base) + t;
        uint2* q = (uint2*)(g_Utf + base) + t;
        float2 a = make_float2(0.f, 0.f);
        #pragma unroll 4
        for (int s = 0; s < 128; ++s) {
            float2 f = p[(size_t)s * 256];
            a.x += f.x; a.y += f.y;
            uint2 u; u.x = tf32r(f.x); u.y = tf32r(f.y);
            q[(size_t)s * 256] = u;
        }
        *(float2*)(g_tp + ((size_t)sc * B_ + b) * DIN + t * 2) = a;
    }
}

// ---------------- fused out + w (fp32; sums the two v partials) ----------------
__global__ __launch_bounds__(512) void outw_k(float* __restrict__ out, int bcast, int dow) {
    int n  = blockIdx.x;
    int b0 = blockIdx.y * 8;
    __shared__ __align__(16) float sv[8][DIN];
    __shared__ float so[8][DCAP];
    int t = threadIdx.x, w = t >> 5, lane = t & 31;
    const float* Wn = g_Wt + (size_t)n * DCAP * DIN;

    #pragma unroll
    for (int r = 0; r < 8; ++r) {
        int idx = r * 512 + t;
        int bb = idx >> 9, pos = idx & 511;
        int b = b0 + bb;
        float val;
        if (bcast)
            val = g_tp[(size_t)b * DIN + pos]
                + g_tp[((size_t)B_ + b) * DIN + pos]
                + g_tp[((size_t)2 * B_ + b) * DIN + pos]
                + g_tp[((size_t)3 * B_ + b) * DIN + pos];
        else
            val = g_vp[((size_t)b * NCAP + n) * DIN + pos]
                + g_vp[((size_t)(B_ + b) * NCAP + n) * DIN + pos];
        sv[bb][pos] = val;
    }
    __syncthreads();

    #pragma unroll
    for (int r = 0; r < 4; ++r) {
        int d = r * 16 + w;
        const float4* wp = (const float4*)(Wn + (size_t)d * DIN);
        float acc[8] = {};
        #pragma unroll
        for (int q = 0; q < 4; ++q) {
            float4 wv = wp[lane + q * 32];
            #pragma unroll
            for (int bb = 0; bb < 8; ++bb) {
                float4 vv = ((const float4*)sv[bb])[lane + q * 32];
                acc[bb] += wv.x * vv.x + wv.y * vv.y + wv.z * vv.z + wv.w * vv.w;
            }
        }
        #pragma unroll
        for (int bb = 0; bb < 8; ++bb) {
            #pragma unroll
            for (int off = 16; off; off >>= 1)
                acc[bb] += __shfl_xor_sync(0xffffffffu, acc[bb], off);
        }
        if (lane == 0) {
            #pragma unroll
            for (int bb = 0; bb < 8; ++bb) so[bb][d] = acc[bb];
        }
    }
    __syncthreads();

    if (w < 8) {
        int b = b0 + w;
        float o1 = so[w][lane], o2 = so[w][lane + 32];
        if (bcast) { o1 *= (1.f / 32.f); o2 *= (1.f / 32.f); }
        float sq = o1 * o1 + o2 * o2;
        #pragma unroll
        for (int off = 16; off; off >>= 1) sq += __shfl_xor_sync(0xffffffffu, sq, off);
        float rn = rsqrtf(sq + EPSQ);
        o1 *= rn; o2 *= rn;
        out[((size_t)b * NCAP + n) * DCAP + lane]      = o1;
        out[((size_t)b * NCAP + n) * DCAP + lane + 32] = o2;
        so[w][lane]      = o1;
        so[w][lane + 32] = o2;
    }
    __syncthreads();

    if (dow) {
        int i = t;
        float acc[8] = {};
        #pragma unroll 8
        for (int d = 0; d < DCAP; ++d) {
            float wt = Wn[(size_t)d * DIN + i];
            #pragma unroll
            for (int bb = 0; bb < 8; ++bb) acc[bb] += so[bb][d] * wt;
        }
        #pragma unroll
        for (int bb = 0; bb < 8; ++bb)
            g_w[((size_t)(b0 + bb) * DIN + i) * NCAP + n] = acc[bb];
    }
}

// ---------------- tf32 MMA logit partials: 128s x 32n, K = 256 i's ----------------
// grid (4 s-tiles, 2 i-halves, 64 b) = 512 blocks, 4 warps; warp = 32s x 32n.
__global__ __launch_bounds__(128, 4) void blogmma_k() {
    int s0 = blockIdx.x * 128;
    int ih = blockIdx.y * 256;
    int b  = blockIdx.z;
    __shared__ uint32_t su[128 * 36];   // tf32 bits [s][k]
    __shared__ uint32_t sw[32 * 36];    // tf32 bits [k][n]
    int t = threadIdx.x, w = t >> 5, lane = t & 31;
    int g = lane >> 2, tg = lane & 3;
    int wrow = w * 32;
    int lrow = t >> 2, lc = (t & 3) * 8;
    const uint32_t* Ub = g_Utf + ((size_t)b * S_ + s0) * DIN + ih;
    const float*    wb = g_w   + (size_t)b * DIN * NCAP + (size_t)ih * NCAP;
    float c[2][4][4] = {};
    uint4 pu[8];
    float4 pw[2];
    #pragma unroll
    for (int r = 0; r < 4; ++r) {
        pu[2 * r]     = *(const uint4*)(Ub + (size_t)(lrow + 32 * r) * DIN + lc);
        pu[2 * r + 1] = *(const uint4*)(Ub + (size_t)(lrow + 32 * r) * DIN + lc + 4);
    }
    pw[0] = *(const float4*)(wb + (size_t)lrow * NCAP + lc);
    pw[1] = *(const float4*)(wb + (size_t)lrow * NCAP + lc + 4);

    #pragma unroll 1
    for (int ch = 0; ch < 8; ++ch) {
        __syncthreads();
        #pragma unroll
        for (int r = 0; r < 4; ++r) {
            uint32_t* d0 = &su[(lrow + 32 * r) * 36 + lc];
            *(uint4*)(d0)     = pu[2 * r];
            *(uint4*)(d0 + 4) = pu[2 * r + 1];
        }
        {
            uint32_t* d0 = &sw[lrow * 36 + lc];
            float4 a = pw[0], bq = pw[1];
            d0[0] = tf32r(a.x);  d0[1] = tf32r(a.y);  d0[2] = tf32r(a.z);  d0[3] = tf32r(a.w);
            d0[4] = tf32r(bq.x); d0[5] = tf32r(bq.y); d0[6] = tf32r(bq.z); d0[7] = tf32r(bq.w);
        }
        __syncthreads();
        if (ch < 7) {
            int i0 = (ch + 1) * 32;
            #pragma unroll
            for (int r = 0; r < 4; ++r) {
                pu[2 * r]     = *(const uint4*)(Ub + (size_t)(lrow + 32 * r) * DIN + i0 + lc);
                pu[2 * r + 1] = *(const uint4*)(Ub + (size_t)(lrow + 32 * r) * DIN + i0 + lc + 4);
            }
            pw[0] = *(const float4*)(wb + (size_t)(i0 + lrow) * NCAP + lc);
            pw[1] = *(const float4*)(wb + (size_t)(i0 + lrow) * NCAP + lc + 4);
        }
        #pragma unroll
        for (int ks = 0; ks < 4; ++ks) {
            int k0 = ks * 8;
            uint32_t bf[4][2];
            #pragma unroll
            for (int nt = 0; nt < 4; ++nt) {
                bf[nt][0] = sw[(k0 + tg) * 36 + nt * 8 + g];
                bf[nt][1] = sw[(k0 + tg + 4) * 36 + nt * 8 + g];
            }
            #pragma unroll
            for (int mt = 0; mt < 2; ++mt) {
                int r0 = wrow + mt * 16;
                uint32_t a0 = su[(r0 + g)     * 36 + k0 + tg];
                uint32_t a1 = su[(r0 + g + 8) * 36 + k0 + tg];
                uint32_t a2 = su[(r0 + g)     * 36 + k0 + tg + 4];
                uint32_t a3 = su[(r0 + g + 8) * 36 + k0 + tg + 4];
                #pragma unroll
                for (int nt = 0; nt < 4; ++nt)
                    mma_tf32(c[mt][nt][0], c[mt][nt][1], c[mt][nt][2], c[mt][nt][3],
                             a0, a1, a2, a3, bf[nt][0], bf[nt][1]);
            }
        }
    }
    // raw partial store
    float* lbase = g_l + (((size_t)blockIdx.y * B_ + b) * S_ + s0) * NCAP;
    #pragma unroll
    for (int mt = 0; mt < 2; ++mt) {
        #pragma unroll
        for (int half = 0; half < 2; ++half) {
            int row = wrow + mt * 16 + g + half * 8;
            float* cr = lbase + (size_t)row * NCAP + 2 * tg;
            #pragma unroll
            for (int nt = 0; nt < 4; ++nt)
                *(float2*)(cr + nt * 8) =
                    make_float2(c[mt][nt][half * 2], c[mt][nt][half * 2 + 1]);
        }
    }
}

// ---------------- tf32 MMA v partials: 128i x 32n, K = 256 s's; softmax in loader ------
// grid (4 i-tiles, 2 s-halves, 64 b) = 512 blocks, 4 warps; warp = 32i x 32n.
__global__ __launch_bounds__(128, 4) void vmma_k() {
    int i0 = blockIdx.x * 128;
    int sh = blockIdx.y * 256;
    int b  = blockIdx.z;
    __shared__ uint32_t su[32 * 132];   // tf32 bits [s][i] (reused as vsm[128][33])
    __shared__ uint32_t scm[32 * 36];   // tf32 bits [s][n]
    int t = threadIdx.x, w = t >> 5, lane = t & 31;
    int g = lane >> 2, tg = lane & 3;
    int wi = w * 32;
    int lrow = t >> 2, l4 = (t & 3) * 4, lc = (t & 3) * 8;
    const uint32_t* Ub = g_Utf + (size_t)b * S_ * DIN;
    const float* l0 = g_l + ((size_t)b * S_ + sh) * NCAP;
    const float* l1 = g_l + (((size_t)B_ + b) * S_ + sh) * NCAP;
    float c[2][4][4] = {};
    uint4 pu[8];
    float4 p0[2], p1[2];
    #pragma unroll
    for (int q = 0; q < 8; ++q)
        pu[q] = *(const uint4*)(Ub + (size_t)(sh + lrow) * DIN + i0 + l4 + 16 * q);
    p0[0] = *(const float4*)(l0 + (size_t)lrow * NCAP + lc);
    p0[1] = *(const float4*)(l0 + (size_t)lrow * NCAP + lc + 4);
    p1[0] = *(const float4*)(l1 + (size_t)lrow * NCAP + lc);
    p1[1] = *(const float4*)(l1 + (size_t)lrow * NCAP + lc + 4);

    #pragma unroll 1
    for (int ch = 0; ch < 8; ++ch) {
        __syncthreads();
        #pragma unroll
        for (int q = 0; q < 8; ++q)
            *(uint4*)&su[lrow * 132 + l4 + 16 * q] = pu[q];
        {   // combine partials + softmax over n (4 lanes per s-row: xor 1,2) + tf32
            float v0 = p0[0].x + p1[0].x, v1 = p0[0].y + p1[0].y;
            float v2 = p0[0].z + p1[0].z, v3 = p0[0].w + p1[0].w;
            float v4 = p0[1].x + p1[1].x, v5 = p0[1].y + p1[1].y;
            float v6 = p0[1].z + p1[1].z, v7 = p0[1].w + p1[1].w;
            float m = fmaxf(fmaxf(fmaxf(v0, v1), fmaxf(v2, v3)),
                            fmaxf(fmaxf(v4, v5), fmaxf(v6, v7)));
            m = fmaxf(m, __shfl_xor_sync(0xffffffffu, m, 1));
            m = fmaxf(m, __shfl_xor_sync(0xffffffffu, m, 2));
            float e0 = __expf(v0 - m), e1 = __expf(v1 - m), e2 = __expf(v2 - m), e3 = __expf(v3 - m);
            float e4 = __expf(v4 - m), e5 = __expf(v5 - m), e6 = __expf(v6 - m), e7 = __expf(v7 - m);
            float sm = e0 + e1 + e2 + e3 + e4 + e5 + e6 + e7;
            sm += __shfl_xor_sync(0xffffffffu, sm, 1);
            sm += __shfl_xor_sync(0xffffffffu, sm, 2);
            float inv = 1.f / sm;
            uint32_t* d0 = &scm[lrow * 36 + lc];
            d0[0] = tf32r(e0 * inv); d0[1] = tf32r(e1 * inv);
            d0[2] = tf32r(e2 * inv); d0[3] = tf32r(e3 * inv);
            d0[4] = tf32r(e4 * inv); d0[5] = tf32r(e5 * inv);
            d0[6] = tf32r(e6 * inv); d0[7] = tf32r(e7 * inv);
        }
        __syncthreads();
        if (ch < 7) {
            int s1 = sh + (ch + 1) * 32;
            #pragma unroll
            for (int q = 0; q < 8; ++q)
                pu[q] = *(const uint4*)(Ub + (size_t)(s1 + lrow) * DIN + i0 + l4 + 16 * q);
            size_t off = (size_t)((ch + 1) * 32 + lrow) * NCAP + lc;
            p0[0] = *(const float4*)(l0 + off);
            p0[1] = *(const float4*)(l0 + off + 4);
            p1[0] = *(const float4*)(l1 + off);
            p1[1] = *(const float4*)(l1 + off + 4);
        }
        #pragma unroll
        for (int ks = 0; ks < 4; ++ks) {
            int k0 = ks * 8;
            uint32_t bf[4][2];
            #pragma unroll
            for (int nt = 0; nt < 4; ++nt) {
                bf[nt][0] = scm[(k0 + tg) * 36 + nt * 8 + g];
                bf[nt][1] = scm[(k0 + tg + 4) * 36 + nt * 8 + g];
            }
            #pragma unroll
            for (int mt = 0; mt < 2; ++mt) {
                int ib = wi + mt * 16;
                uint32_t a0 = su[(k0 + tg)     * 132 + ib + g];
                uint32_t a1 = su[(k0 + tg)     * 132 + ib + g + 8];
                uint32_t a2 = su[(k0 + tg + 4) * 132 + ib + g];
                uint32_t a3 = su[(k0 + tg + 4) * 132 + ib + g + 8];
                #pragma unroll
                for (int nt = 0; nt < 4; ++nt)
                    mma_tf32(c[mt][nt][0], c[mt][nt][1], c[mt][nt][2], c[mt][nt][3],
                             a0, a1, a2, a3, bf[nt][0], bf[nt][1]);
            }
        }
    }
    // transpose v^T[i][n] -> v[n][i] via smem, coalesced partial store
    __syncthreads();
    float* vsm = (float*)su;
    #pragma unroll
    for (int mt = 0; mt < 2; ++mt) {
        int ib = wi + mt * 16;
        #pragma unroll
        for (int nt = 0; nt < 4; ++nt) {
            int nc = nt * 8 + 2 * tg;
            vsm[(ib + g)     * 33 + nc]     = c[mt][nt][0];
            vsm[(ib + g)     * 33 + nc + 1] = c[mt][nt][1];
            vsm[(ib + g + 8) * 33 + nc]     = c[mt][nt][2];
            vsm[(ib + g + 8) * 33 + nc + 1] = c[mt][nt][3];
        }
    }
    __syncthreads();
    {
        int n = t >> 2, igrp = t & 3;
        float* vb = g_vp + ((size_t)(blockIdx.y * B_ + b) * NCAP + n) * DIN + i0;
        #pragma unroll
        for (int q = 0; q < 8; ++q) {
            int i4 = igrp * 4 + q * 16;
            float4 o = make_float4(vsm[(i4 + 0) * 33 + n], vsm[(i4 + 1) * 33 + n],
                                   vsm[(i4 + 2) * 33 + n], vsm[(i4 + 3) * 33 + n]);
            *(float4*)(vb + i4) = o;
        }
    }
}

// ---------------- launch ----------------
extern "C" void kernel_launch(void* const* d_in, const int* in_sizes, int n_in,
                              void* d_out, int out_size) {
    const float* U = (const float*)d_in[0];   // (64, 512, 512)
    const float* W = (const float*)d_in[1];   // (512, 2048)
    float* out = (float*)d_out;               // (64, 32, 64)

    prep_k<<<512, 256>>>(U, W);
    outw_k<<<dim3(32, 8), 512>>>(out, 1, 1);             // iteration 0 + w0
    for (int it = 0; it < 2; ++it) {
        blogmma_k<<<dim3(4, 2, 64), 128>>>();
        vmma_k<<<dim3(4, 2, 64), 128>>>();
        outw_k<<<dim3(32, 8), 512>>>(out, 0, it == 0);   // out + (w for iter 1 only)
    }
}

// round 10
// speedup vs baseline: 1.1650x; 1.1650x over previous
#include <cuda_runtime.h>
#include <cuda_fp16.h>
#include <cstdint>

#define B_    64
#define S_    512
#define DIN   512
#define NCAP  32
#define DCAP  64
#define EPSQ  1e-7f

// ---------------- scratch (device globals; no allocations) ----------------
__device__ __half g_Uh[B_ * S_ * DIN];         // fp16 copy of U (converted once) ~34MB
__device__ float  g_Wt[NCAP * DCAP * DIN];     // W transposed: [n][d][i]
__device__ float  g_tp[4 * B_ * DIN];          // partial column sums of U
__device__ float  g_w[B_ * DIN * NCAP];        // w[b][i][n]
__device__ __half g_ch[B_ * S_ * NCAP];        // c[b][s][n] fp16 (post-softmax)
__device__ float  g_v[B_ * NCAP * DIN];        // v[b][n][i]

// ---------------- fp16 m16n8k16 MMA ----------------
__device__ __forceinline__ void mma_f16(float& c0, float& c1, float& c2, float& c3,
                                        uint32_t a0, uint32_t a1, uint32_t a2, uint32_t a3,
                                        uint32_t b0, uint32_t b1) {
    asm("mma.sync.aligned.m16n8k16.row.col.f32.f16.f16.f32 "
        "{%0,%1,%2,%3}, {%4,%5,%6,%7}, {%8,%9}, {%0,%1,%2,%3};"
        : "+f"(c0), "+f"(c1), "+f"(c2), "+f"(c3)
        : "r"(a0), "r"(a1), "r"(a2), "r"(a3), "r"(b0), "r"(b1));
}

// ---------------- prep: blocks 0..255 transpose W; 256..511 colsum U + fp16 convert ----
__global__ __launch_bounds__(256) void prep_k(const float* __restrict__ U,
                                              const float* __restrict__ W) {
    int t = threadIdx.x;
    if (blockIdx.x < 256) {
        int n  = blockIdx.x >> 3;
        int i0 = (blockIdx.x & 7) * 64;
        __shared__ float sm[64 * 65];
        #pragma unroll
        for (int r = 0; r < 16; ++r) {
            int idx = r * 256 + t;
            int d = idx & 63, ii = idx >> 6;
            sm[d * 65 + ii] = W[(size_t)(i0 + ii) * 2048 + n * 64 + d];
        }
        __syncthreads();
        #pragma unroll
        for (int r = 0; r < 16; ++r) {
            int idx = r * 256 + t;
            int ii = idx & 63, d = idx >> 6;
            g_Wt[((size_t)n * 64 + d) * 512 + i0 + ii] = sm[d * 65 + ii];
        }
    } else {
        int idx = blockIdx.x - 256;
        int b = idx & 63, sc = idx >> 6;
        size_t base = ((size_t)b * S_ + sc * 128) * DIN;
        const float2* p = (const float2*)(U + base) + t;
        __half2* qh = (__half2*)(g_Uh + base) + t;
        float2 a = make_float2(0.f, 0.f);
        #pragma unroll 4
        for (int s = 0; s < 128; ++s) {
            float2 f = p[(size_t)s * 256];
            a.x += f.x; a.y += f.y;
            qh[(size_t)s * 256] = __floats2half2_rn(f.x, f.y);
        }
        *(float2*)(g_tp + ((size_t)sc * B_ + b) * DIN + t * 2) = a;
    }
}

// ---------------- fused out + w (fp32, unchanged from R8) ----------------
__global__ __launch_bounds__(512) void outw_k(float* __restrict__ out, int bcast, int dow) {
    int n  = blockIdx.x;
    int b0 = blockIdx.y * 8;
    __shared__ __align__(16) float sv[8][DIN];
    __shared__ float so[8][DCAP];
    int t = threadIdx.x, w = t >> 5, lane = t & 31;
    const float* Wn = g_Wt + (size_t)n * DCAP * DIN;

    #pragma unroll
    for (int r = 0; r < 8; ++r) {
        int idx = r * 512 + t;
        int bb = idx >> 9, pos = idx & 511;
        int b = b0 + bb;
        float val;
        if (bcast)
            val = g_tp[(size_t)b * DIN + pos]
                + g_tp[((size_t)B_ + b) * DIN + pos]
                + g_tp[((size_t)2 * B_ + b) * DIN + pos]
                + g_tp[((size_t)3 * B_ + b) * DIN + pos];
        else
            val = g_v[((size_t)b * NCAP + n) * DIN + pos];
        sv[bb][pos] = val;
    }
    __syncthreads();

    #pragma unroll
    for (int r = 0; r < 4; ++r) {
        int d = r * 16 + w;
        const float4* wp = (const float4*)(Wn + (size_t)d * DIN);
        float acc[8] = {};
        #pragma unroll
        for (int q = 0; q < 4; ++q) {
            float4 wv = wp[lane + q * 32];
            #pragma unroll
            for (int bb = 0; bb < 8; ++bb) {
                float4 vv = ((const float4*)sv[bb])[lane + q * 32];
                acc[bb] += wv.x * vv.x + wv.y * vv.y + wv.z * vv.z + wv.w * vv.w;
            }
        }
        #pragma unroll
        for (int bb = 0; bb < 8; ++bb) {
            #pragma unroll
            for (int off = 16; off; off >>= 1)
                acc[bb] += __shfl_xor_sync(0xffffffffu, acc[bb], off);
        }
        if (lane == 0) {
            #pragma unroll
            for (int bb = 0; bb < 8; ++bb) so[bb][d] = acc[bb];
        }
    }
    __syncthreads();

    if (w < 8) {
        int b = b0 + w;
        float o1 = so[w][lane], o2 = so[w][lane + 32];
        if (bcast) { o1 *= (1.f / 32.f); o2 *= (1.f / 32.f); }
        float sq = o1 * o1 + o2 * o2;
        #pragma unroll
        for (int off = 16; off; off >>= 1) sq += __shfl_xor_sync(0xffffffffu, sq, off);
        float rn = rsqrtf(sq + EPSQ);
        o1 *= rn; o2 *= rn;
        out[((size_t)b * NCAP + n) * DCAP + lane]      = o1;
        out[((size_t)b * NCAP + n) * DCAP + lane + 32] = o2;
        so[w][lane]      = o1;
        so[w][lane + 32] = o2;
    }
    __syncthreads();

    if (dow) {
        int i = t;
        float acc[8] = {};
        #pragma unroll 8
        for (int d = 0; d < DCAP; ++d) {
            float wt = Wn[(size_t)d * DIN + i];
            #pragma unroll
            for (int bb = 0; bb < 8; ++bb) acc[bb] += so[bb][d] * wt;
        }
        #pragma unroll
        for (int bb = 0; bb < 8; ++bb)
            g_w[((size_t)(b0 + bb) * DIN + i) * NCAP + n] = acc[bb];
    }
}

// ---------------- fp16 MMA: logits[s,n] = U[s,:]·w[:,n], softmax fused ----------------
// grid (4 s-tiles, 64 b), block 128 (4 warps). Tile 128s x 32n, K=512 in chunks of 32.
__global__ __launch_bounds__(128, 4) void blogmma_k() {
    int s0 = blockIdx.x * 128;
    int b  = blockIdx.y;
    __shared__ __align__(16) __half su[128 * 40];  // [s][k], stride 40 halfs (conflict-free)
    __shared__ __align__(16) __half sw[32 * 40];   // [n][k]
    int t = threadIdx.x, w = t >> 5, lane = t & 31;
    int g = lane >> 2, tg = lane & 3;
    int wrow = w * 32;
    int lr = t >> 2, lq = t & 3;    // loader coords
    const __half* Ub = g_Uh + ((size_t)b * S_ + s0) * DIN;
    const float*  wb = g_w  + (size_t)b * DIN * NCAP;
    float c[2][4][4] = {};
    uint4 pu[4];
    float4 pw[2];
    #pragma unroll
    for (int r = 0; r < 4; ++r)
        pu[r] = *(const uint4*)(Ub + (size_t)(lr + 32 * r) * DIN + lq * 8);
    pw[0] = *(const float4*)(wb + (size_t)lr * NCAP + lq * 8);
    pw[1] = *(const float4*)(wb + (size_t)lr * NCAP + lq * 8 + 4);

    #pragma unroll 1
    for (int ch = 0; ch < 16; ++ch) {
        __syncthreads();
        #pragma unroll
        for (int r = 0; r < 4; ++r)
            *(uint4*)&su[(lr + 32 * r) * 40 + lq * 8] = pu[r];
        {   // w tile: rows k (i), transposed into [n][k], fp16
            float wf[8] = {pw[0].x, pw[0].y, pw[0].z, pw[0].w,
                           pw[1].x, pw[1].y, pw[1].z, pw[1].w};
            #pragma unroll
            for (int j = 0; j < 8; ++j)
                sw[(lq * 8 + j) * 40 + lr] = __float2half_rn(wf[j]);
        }
        __syncthreads();
        if (ch < 15) {
            int k0 = (ch + 1) * 32;
            #pragma unroll
            for (int r = 0; r < 4; ++r)
                pu[r] = *(const uint4*)(Ub + (size_t)(lr + 32 * r) * DIN + k0 + lq * 8);
            pw[0] = *(const float4*)(wb + (size_t)(k0 + lr) * NCAP + lq * 8);
            pw[1] = *(const float4*)(wb + (size_t)(k0 + lr) * NCAP + lq * 8 + 4);
        }
        #pragma unroll
        for (int ks = 0; ks < 32; ks += 16) {
            uint32_t bf[4][2];
            #pragma unroll
            for (int nt = 0; nt < 4; ++nt) {
                bf[nt][0] = *(const uint32_t*)&sw[(nt * 8 + g) * 40 + ks + 2 * tg];
                bf[nt][1] = *(const uint32_t*)&sw[(nt * 8 + g) * 40 + ks + 2 * tg + 8];
            }
            #pragma unroll
            for (int mt = 0; mt < 2; ++mt) {
                int r0 = wrow + mt * 16;
                uint32_t a0 = *(const uint32_t*)&su[(r0 + g)     * 40 + ks + 2 * tg];
                uint32_t a1 = *(const uint32_t*)&su[(r0 + g + 8) * 40 + ks + 2 * tg];
                uint32_t a2 = *(const uint32_t*)&su[(r0 + g)     * 40 + ks + 2 * tg + 8];
                uint32_t a3 = *(const uint32_t*)&su[(r0 + g + 8) * 40 + ks + 2 * tg + 8];
                #pragma unroll
                for (int nt = 0; nt < 4; ++nt)
                    mma_f16(c[mt][nt][0], c[mt][nt][1], c[mt][nt][2], c[mt][nt][3],
                            a0, a1, a2, a3, bf[nt][0], bf[nt][1]);
            }
        }
    }
    // softmax over n per s-row (row's 32 n on 4 lanes sharing g: xor 1,2); fp16 store
    __half* cbase = g_ch + ((size_t)b * S_ + s0) * NCAP;
    #pragma unroll
    for (int mt = 0; mt < 2; ++mt) {
        #pragma unroll
        for (int half = 0; half < 2; ++half) {
            int row = wrow + mt * 16 + g + half * 8;
            float v0 = c[mt][0][half * 2], v1 = c[mt][0][half * 2 + 1];
            float v2 = c[mt][1][half * 2], v3 = c[mt][1][half * 2 + 1];
            float v4 = c[mt][2][half * 2], v5 = c[mt][2][half * 2 + 1];
            float v6 = c[mt][3][half * 2], v7 = c[mt][3][half * 2 + 1];
            float m = fmaxf(fmaxf(fmaxf(v0, v1), fmaxf(v2, v3)),
                            fmaxf(fmaxf(v4, v5), fmaxf(v6, v7)));
            m = fmaxf(m, __shfl_xor_sync(0xffffffffu, m, 1));
            m = fmaxf(m, __shfl_xor_sync(0xffffffffu, m, 2));
            float e0 = __expf(v0 - m), e1 = __expf(v1 - m), e2 = __expf(v2 - m), e3 = __expf(v3 - m);
            float e4 = __expf(v4 - m), e5 = __expf(v5 - m), e6 = __expf(v6 - m), e7 = __expf(v7 - m);
            float sm = e0 + e1 + e2 + e3 + e4 + e5 + e6 + e7;
            sm += __shfl_xor_sync(0xffffffffu, sm, 1);
            sm += __shfl_xor_sync(0xffffffffu, sm, 2);
            float inv = 1.f / sm;
            __half2* cr = (__half2*)(cbase + (size_t)row * NCAP + 2 * tg);
            cr[0]  = __floats2half2_rn(e0 * inv, e1 * inv);
            cr[4]  = __floats2half2_rn(e2 * inv, e3 * inv);
            cr[8]  = __floats2half2_rn(e4 * inv, e5 * inv);
            cr[12] = __floats2half2_rn(e6 * inv, e7 * inv);
        }
    }
}

// ---------------- fp16 MMA: v[n,i] = sum_s c[s,n] U[s,i] (v^T then transpose) ----------
// grid (4 i-tiles, 64 b), block 128 (4 warps). Tile 128i x 32n, K=s=512 in chunks of 32.
__global__ __launch_bounds__(128, 4) void vmma_k() {
    int i0 = blockIdx.x * 128;
    int b  = blockIdx.y;
    __shared__ __align__(16) unsigned char smraw[17024];
    __half* sut = (__half*)smraw;                 // [i][s] 128x40 halfs (10240B)
    __half* scm = (__half*)(smraw + 10240);       // [n][s] 32x40 halfs (2560B)
    float*  vsm = (float*)smraw;                  // epilogue reuse: 128x33 floats (16896B)
    int t = threadIdx.x, w = t >> 5, lane = t & 31;
    int g = lane >> 2, tg = lane & 3;
    int wi = w * 32;
    int lr = t >> 2, lq = t & 3;
    const __half* Ub = g_Uh + (size_t)b * S_ * DIN;
    const __half* cb = g_ch + (size_t)b * S_ * NCAP;
    float c[2][4][4] = {};
    uint4 pu[4], pc;
    #pragma unroll
    for (int r = 0; r < 4; ++r)
        pu[r] = *(const uint4*)(Ub + (size_t)lr * DIN + i0 + (lq + 4 * r) * 8);
    pc = *(const uint4*)(cb + (size_t)lr * NCAP + lq * 8);

    #pragma unroll 1
    for (int ch = 0; ch < 16; ++ch) {
        __syncthreads();
        #pragma unroll
        for (int r = 0; r < 4; ++r) {   // transpose-stage U: [s][i] -> sut[i][s]
            const __half* h = (const __half*)&pu[r];
            int ib = (lq + 4 * r) * 8;
            #pragma unroll
            for (int j = 0; j < 8; ++j)
                sut[(ib + j) * 40 + lr] = h[j];
        }
        {   // transpose-stage c: [s][n] -> scm[n][s]
            const __half* h = (const __half*)&pc;
            #pragma unroll
            for (int j = 0; j < 8; ++j)
                scm[(lq * 8 + j) * 40 + lr] = h[j];
        }
        __syncthreads();
        if (ch < 15) {
            int s1 = (ch + 1) * 32;
            #pragma unroll
            for (int r = 0; r < 4; ++r)
                pu[r] = *(const uint4*)(Ub + (size_t)(s1 + lr) * DIN + i0 + (lq + 4 * r) * 8);
            pc = *(const uint4*)(cb + (size_t)(s1 + lr) * NCAP + lq * 8);
        }
        #pragma unroll
        for (int ks = 0; ks < 32; ks += 16) {
            uint32_t bf[4][2];
            #pragma unroll
            for (int nt = 0; nt < 4; ++nt) {
                bf[nt][0] = *(const uint32_t*)&scm[(nt * 8 + g) * 40 + ks + 2 * tg];
                bf[nt][1] = *(const uint32_t*)&scm[(nt * 8 + g) * 40 + ks + 2 * tg + 8];
            }
            #pragma unroll
            for (int mt = 0; mt < 2; ++mt) {
                int ib = wi + mt * 16;
                uint32_t a0 = *(const uint32_t*)&sut[(ib + g)     * 40 + ks + 2 * tg];
                uint32_t a1 = *(const uint32_t*)&sut[(ib + g + 8) * 40 + ks + 2 * tg];
                uint32_t a2 = *(const uint32_t*)&sut[(ib + g)     * 40 + ks + 2 * tg + 8];
                uint32_t a3 = *(const uint32_t*)&sut[(ib + g + 8) * 40 + ks + 2 * tg + 8];
                #pragma unroll
                for (int nt = 0; nt < 4; ++nt)
                    mma_f16(c[mt][nt][0], c[mt][nt][1], c[mt][nt][2], c[mt][nt][3],
                            a0, a1, a2, a3, bf[nt][0], bf[nt][1]);
            }
        }
    }
    // transpose v^T[i][n] -> v[n][i] via smem, coalesced store
    __syncthreads();
    #pragma unroll
    for (int mt = 0; mt < 2; ++mt) {
        int ib = wi + mt * 16;
        #pragma unroll
        for (int nt = 0; nt < 4; ++nt) {
            int nc = nt * 8 + 2 * tg;
            vsm[(ib + g)     * 33 + nc]     = c[mt][nt][0];
            vsm[(ib + g)     * 33 + nc + 1] = c[mt][nt][1];
            vsm[(ib + g + 8) * 33 + nc]     = c[mt][nt][2];
            vsm[(ib + g + 8) * 33 + nc + 1] = c[mt][nt][3];
        }
    }
    __syncthreads();
    {
        int n = t >> 2, igrp = t & 3;
        float* vb = g_v + ((size_t)b * NCAP + n) * DIN + i0;
        #pragma unroll
        for (int q = 0; q < 8; ++q) {
            int i4 = igrp * 4 + q * 16;
            float4 o = make_float4(vsm[(i4 + 0) * 33 + n], vsm[(i4 + 1) * 33 + n],
                                   vsm[(i4 + 2) * 33 + n], vsm[(i4 + 3) * 33 + n]);
            *(float4*)(vb + i4) = o;
        }
    }
}

// ---------------- launch ----------------
extern "C" void kernel_launch(void* const* d_in, const int* in_sizes, int n_in,
                              void* d_out, int out_size) {
    const float* U = (const float*)d_in[0];   // (64, 512, 512)
    const float* W = (const float*)d_in[1];   // (512, 2048)
    float* out = (float*)d_out;               // (64, 32, 64)

    prep_k<<<512, 256>>>(U, W);
    outw_k<<<dim3(32, 8), 512>>>(out, 1, 1);             // iteration 0 + w0
    for (int it = 0; it < 2; ++it) {
        blogmma_k<<<dim3(4, 64), 128>>>();
        vmma_k<<<dim3(4, 64), 128>>>();
        outw_k<<<dim3(32, 8), 512>>>(out, 0, it == 0);   // out + (w for iter 1 only)
    }
}